// round 11
// baseline (speedup 1.0000x reference)
#include <cuda_runtime.h>

// SimpleSSM: x [8, 4096, 1024] fp32; per-channel diagonal SSM + LayerNorm over dim.
constexpr int NB = 8;
constexpr int NT = 4096;
constexpr int ND = 1024;
constexpr int LCH = 64;                 // timesteps per chunk
constexpr int NCHUNK = NT / LCH;        // 64 chunks per batch
constexpr int HB = 4;                   // batches per half
constexpr int HBLK = HB * NCHUNK;       // 256 blocks per half-kernel
constexpr float EPS = 1e-5f;

// Persistent chunk aggregates, indexed by global (b, c). 2 MB.
__device__ float g_S[(size_t)NB * NCHUNK * ND];

__device__ __forceinline__ float4 ld_lastuse4(const float4* p) {
    float4 v;
    asm("ld.global.lu.v4.f32 {%0,%1,%2,%3}, [%4];"
        : "=f"(v.x), "=f"(v.y), "=f"(v.z), "=f"(v.w) : "l"(p));
    return v;
}
__device__ __forceinline__ float4 ldcg4(const float* p) {
    return __ldcg(reinterpret_cast<const float4*>(p));
}

// ---------------------------------------------------------------------------
// k_chunk(half): local aggregates for the 4 batches of this half.
// 256 blocks x 256 threads. Pure streaming, no sync.
// ---------------------------------------------------------------------------
__global__ void __launch_bounds__(256, 4) k_chunk(const float* __restrict__ x,
                                                  const float* __restrict__ A,
                                                  const float* __restrict__ B,
                                                  int half) {
    const int c = blockIdx.x % NCHUNK;
    const int b = half * HB + blockIdx.x / NCHUNK;
    const int d4 = threadIdx.x * 4;

    const float4 a  = *reinterpret_cast<const float4*>(A + d4);
    const float4 bb = *reinterpret_cast<const float4*>(B + d4);

    const float4* xp = reinterpret_cast<const float4*>(
        x + ((size_t)b * NT + (size_t)c * LCH) * ND + d4);

    float4 S = make_float4(0.f, 0.f, 0.f, 0.f);
    #pragma unroll 8
    for (int t = 0; t < LCH; t++) {
        float4 xv = xp[(size_t)t * (ND / 4)];
        S.x = fmaf(a.x, S.x, bb.x * xv.x);
        S.y = fmaf(a.y, S.y, bb.y * xv.y);
        S.z = fmaf(a.z, S.z, bb.z * xv.z);
        S.w = fmaf(a.w, S.w, bb.w * xv.w);
    }
    *reinterpret_cast<float4*>(&g_S[((size_t)b * NCHUNK + c) * ND + d4]) = S;
}

// ---------------------------------------------------------------------------
// k_fuse(half): fold h_start from L2-hot aggregates (no separate scan kernel),
// then re-run the recurrence on the still-L2-resident x chunk + fused LN.
// The kernel boundary between k_chunk and k_fuse is the grid barrier.
// ---------------------------------------------------------------------------
__global__ void __launch_bounds__(256, 4) k_fuse(const float* __restrict__ x,
                                                 const float* __restrict__ A,
                                                 const float* __restrict__ B,
                                                 const float* __restrict__ C,
                                                 const float* __restrict__ D,
                                                 const float* __restrict__ G,
                                                 const float* __restrict__ Be,
                                                 float* __restrict__ out,
                                                 int half) {
    const int c = blockIdx.x % NCHUNK;
    const int b = half * HB + blockIdx.x / NCHUNK;
    const int tid  = threadIdx.x;
    const int lane = tid & 31;
    const int wid  = tid >> 5;
    const int d4   = tid * 4;

    const float4 a  = *reinterpret_cast<const float4*>(A + d4);
    const float4 bb = *reinterpret_cast<const float4*>(B + d4);
    const float4 cc = *reinterpret_cast<const float4*>(C + d4);
    const float4 dd = *reinterpret_cast<const float4*>(D + d4);

    // a^LCH (6 squarings)
    float4 aL = a;
    #pragma unroll
    for (int i = 0; i < 6; i++) {
        aL.x *= aL.x; aL.y *= aL.y; aL.z *= aL.z; aL.w *= aL.w;
    }

    // ---- h_start = sum_{k<c} aL^(c-1-k) * S_k (aggregates are L2-hot) ----
    float4 h    = make_float4(0.f, 0.f, 0.f, 0.f);
    float4 coef = make_float4(1.f, 1.f, 1.f, 1.f);
    for (int k = c - 1; k >= 0; k--) {
        float4 Sk = ldcg4(&g_S[((size_t)b * NCHUNK + k) * ND + d4]);
        h.x = fmaf(coef.x, Sk.x, h.x);
        h.y = fmaf(coef.y, Sk.y, h.y);
        h.z = fmaf(coef.z, Sk.z, h.z);
        h.w = fmaf(coef.w, Sk.w, h.w);
        coef.x *= aL.x; coef.y *= aL.y; coef.z *= aL.z; coef.w *= aL.w;
    }

    const size_t base = ((size_t)b * NT + (size_t)c * LCH) * ND + d4;
    const float4* xp = reinterpret_cast<const float4*>(x + base);
    float4* op = reinterpret_cast<float4*>(out + base);

    __shared__ float2 red[2][4][8];   // [parity][timestep j][warp] (sum, sumsq)
    __shared__ float2 mur[2][4];      // [parity][timestep j] (mu, rstd)

    for (int gq = 0; gq < LCH / 4; gq++) {
        const int par = gq & 1;

        // 4 independent x loads (L2 hits: this chunk streamed ~13us ago,
        // and only 64 MB has passed through L2 since).
        float4 xv[4];
        #pragma unroll
        for (int j = 0; j < 4; j++)
            xv[j] = ld_lastuse4(&xp[(size_t)(gq * 4 + j) * (ND / 4)]);

        float4 y[4];
        #pragma unroll
        for (int j = 0; j < 4; j++) {
            h.x = fmaf(a.x, h.x, bb.x * xv[j].x);
            h.y = fmaf(a.y, h.y, bb.y * xv[j].y);
            h.z = fmaf(a.z, h.z, bb.z * xv[j].z);
            h.w = fmaf(a.w, h.w, bb.w * xv[j].w);
            y[j].x = fmaf(cc.x, h.x, dd.x * xv[j].x);
            y[j].y = fmaf(cc.y, h.y, dd.y * xv[j].y);
            y[j].z = fmaf(cc.z, h.z, dd.z * xv[j].z);
            y[j].w = fmaf(cc.w, h.w, dd.w * xv[j].w);
        }

        float s[4], q[4];
        #pragma unroll
        for (int j = 0; j < 4; j++) {
            s[j] = (y[j].x + y[j].y) + (y[j].z + y[j].w);
            q[j] = fmaf(y[j].x, y[j].x,
                   fmaf(y[j].y, y[j].y,
                   fmaf(y[j].z, y[j].z, y[j].w * y[j].w)));
        }
        #pragma unroll
        for (int o = 16; o > 0; o >>= 1) {
            #pragma unroll
            for (int j = 0; j < 4; j++) {
                s[j] += __shfl_xor_sync(0xffffffffu, s[j], o);
                q[j] += __shfl_xor_sync(0xffffffffu, q[j], o);
            }
        }
        if (lane == 0) {
            #pragma unroll
            for (int j = 0; j < 4; j++)
                red[par][j][wid] = make_float2(s[j], q[j]);
        }
        __syncthreads();

        if (wid == 0) {
            const int j = lane >> 3;   // 0..3
            const int w = lane & 7;    // 0..7
            float2 p = red[par][j][w];
            #pragma unroll
            for (int o = 4; o > 0; o >>= 1) {
                p.x += __shfl_xor_sync(0xffffffffu, p.x, o);
                p.y += __shfl_xor_sync(0xffffffffu, p.y, o);
            }
            if (w == 0) {
                const float mu  = p.x * (1.f / ND);
                const float var = fmaf(-mu, mu, p.y * (1.f / ND));
                mur[par][j] = make_float2(mu, rsqrtf(var + EPS));
            }
        }
        __syncthreads();

        const float4 g4 = __ldg(reinterpret_cast<const float4*>(G + d4));
        const float4 be = __ldg(reinterpret_cast<const float4*>(Be + d4));
        #pragma unroll
        for (int j = 0; j < 4; j++) {
            const float2 mr = mur[par][j];
            float4 o;
            o.x = fmaf((y[j].x - mr.x) * mr.y, g4.x, be.x);
            o.y = fmaf((y[j].y - mr.x) * mr.y, g4.y, be.y);
            o.z = fmaf((y[j].z - mr.x) * mr.y, g4.z, be.z);
            o.w = fmaf((y[j].w - mr.x) * mr.y, g4.w, be.w);
            __stcs(&op[(size_t)(gq * 4 + j) * (ND / 4)], o);
        }
    }
}

extern "C" void kernel_launch(void* const* d_in, const int* in_sizes, int n_in,
                              void* d_out, int out_size) {
    const float* x  = (const float*)d_in[0];
    const float* A  = (const float*)d_in[1];
    const float* B  = (const float*)d_in[2];
    const float* C  = (const float*)d_in[3];
    const float* D  = (const float*)d_in[4];
    const float* G  = (const float*)d_in[5];
    const float* Be = (const float*)d_in[6];
    float* out = (float*)d_out;

    // Kernel boundaries provide the grid-wide ordering; no in-kernel
    // inter-block synchronization anywhere.
    k_chunk<<<HBLK, 256>>>(x, A, B, 0);
    k_fuse <<<HBLK, 256>>>(x, A, B, C, D, G, Be, out, 0);
    k_chunk<<<HBLK, 256>>>(x, A, B, 1);
    k_fuse <<<HBLK, 256>>>(x, A, B, C, D, G, Be, out, 1);
}

// round 12
// speedup vs baseline: 1.0033x; 1.0033x over previous
#include <cuda_runtime.h>

// SimpleSSM: x [8, 4096, 1024] fp32; per-channel diagonal SSM + LayerNorm over dim.
constexpr int NB = 8;
constexpr int NT = 4096;
constexpr int ND = 1024;
constexpr int LCH = 64;                 // timesteps per chunk
constexpr int NCHUNK = NT / LCH;        // 64 chunks per batch
constexpr int HB = 4;                   // batches per half
constexpr int HBLK = HB * NCHUNK;       // 256 blocks per half-kernel
constexpr float EPS = 1e-5f;

// Persistent chunk aggregates, indexed by global (b, c). 2 MB.
__device__ float g_S[(size_t)NB * NCHUNK * ND];

__device__ __forceinline__ float4 ld_lastuse4(const float4* p) {
    float4 v;
    asm("ld.global.lu.v4.f32 {%0,%1,%2,%3}, [%4];"
        : "=f"(v.x), "=f"(v.y), "=f"(v.z), "=f"(v.w) : "l"(p));
    return v;
}
__device__ __forceinline__ float4 ldcg4(const float* p) {
    return __ldcg(reinterpret_cast<const float4*>(p));
}

// ---------------------------------------------------------------------------
// k_chunk(half): local aggregates for the 4 batches of this half.
// 256 blocks x 256 threads. Pure streaming, no sync.
// ---------------------------------------------------------------------------
__global__ void __launch_bounds__(256, 4) k_chunk(const float* __restrict__ x,
                                                  const float* __restrict__ A,
                                                  const float* __restrict__ B,
                                                  int half) {
    const int c = blockIdx.x % NCHUNK;
    const int b = half * HB + blockIdx.x / NCHUNK;
    const int d4 = threadIdx.x * 4;

    const float4 a  = *reinterpret_cast<const float4*>(A + d4);
    const float4 bb = *reinterpret_cast<const float4*>(B + d4);

    const float4* xp = reinterpret_cast<const float4*>(
        x + ((size_t)b * NT + (size_t)c * LCH) * ND + d4);

    float4 S = make_float4(0.f, 0.f, 0.f, 0.f);
    #pragma unroll 8
    for (int t = 0; t < LCH; t++) {
        float4 xv = xp[(size_t)t * (ND / 4)];
        S.x = fmaf(a.x, S.x, bb.x * xv.x);
        S.y = fmaf(a.y, S.y, bb.y * xv.y);
        S.z = fmaf(a.z, S.z, bb.z * xv.z);
        S.w = fmaf(a.w, S.w, bb.w * xv.w);
    }
    *reinterpret_cast<float4*>(&g_S[((size_t)b * NCHUNK + c) * ND + d4]) = S;
}

// ---------------------------------------------------------------------------
// k_fuse(half): fold h_start from L2-hot aggregates (no separate scan kernel),
// then re-run the recurrence on the still-L2-resident x chunk + fused LN.
// The kernel boundary between k_chunk and k_fuse is the grid barrier.
// ---------------------------------------------------------------------------
__global__ void __launch_bounds__(256, 4) k_fuse(const float* __restrict__ x,
                                                 const float* __restrict__ A,
                                                 const float* __restrict__ B,
                                                 const float* __restrict__ C,
                                                 const float* __restrict__ D,
                                                 const float* __restrict__ G,
                                                 const float* __restrict__ Be,
                                                 float* __restrict__ out,
                                                 int half) {
    const int c = blockIdx.x % NCHUNK;
    const int b = half * HB + blockIdx.x / NCHUNK;
    const int tid  = threadIdx.x;
    const int lane = tid & 31;
    const int wid  = tid >> 5;
    const int d4   = tid * 4;

    const float4 a  = *reinterpret_cast<const float4*>(A + d4);
    const float4 bb = *reinterpret_cast<const float4*>(B + d4);
    const float4 cc = *reinterpret_cast<const float4*>(C + d4);
    const float4 dd = *reinterpret_cast<const float4*>(D + d4);

    // a^LCH (6 squarings)
    float4 aL = a;
    #pragma unroll
    for (int i = 0; i < 6; i++) {
        aL.x *= aL.x; aL.y *= aL.y; aL.z *= aL.z; aL.w *= aL.w;
    }

    // ---- h_start = sum_{k<c} aL^(c-1-k) * S_k (aggregates are L2-hot) ----
    float4 h    = make_float4(0.f, 0.f, 0.f, 0.f);
    float4 coef = make_float4(1.f, 1.f, 1.f, 1.f);
    for (int k = c - 1; k >= 0; k--) {
        float4 Sk = ldcg4(&g_S[((size_t)b * NCHUNK + k) * ND + d4]);
        h.x = fmaf(coef.x, Sk.x, h.x);
        h.y = fmaf(coef.y, Sk.y, h.y);
        h.z = fmaf(coef.z, Sk.z, h.z);
        h.w = fmaf(coef.w, Sk.w, h.w);
        coef.x *= aL.x; coef.y *= aL.y; coef.z *= aL.z; coef.w *= aL.w;
    }

    const size_t base = ((size_t)b * NT + (size_t)c * LCH) * ND + d4;
    const float4* xp = reinterpret_cast<const float4*>(x + base);
    float4* op = reinterpret_cast<float4*>(out + base);

    __shared__ float2 red[2][4][8];   // [parity][timestep j][warp] (sum, sumsq)
    __shared__ float2 mur[2][4];      // [parity][timestep j] (mu, rstd)

    for (int gq = 0; gq < LCH / 4; gq++) {
        const int par = gq & 1;

        // 4 independent x loads (L2 hits: this chunk streamed ~13us ago,
        // and only 64 MB has passed through L2 since).
        float4 xv[4];
        #pragma unroll
        for (int j = 0; j < 4; j++)
            xv[j] = ld_lastuse4(&xp[(size_t)(gq * 4 + j) * (ND / 4)]);

        float4 y[4];
        #pragma unroll
        for (int j = 0; j < 4; j++) {
            h.x = fmaf(a.x, h.x, bb.x * xv[j].x);
            h.y = fmaf(a.y, h.y, bb.y * xv[j].y);
            h.z = fmaf(a.z, h.z, bb.z * xv[j].z);
            h.w = fmaf(a.w, h.w, bb.w * xv[j].w);
            y[j].x = fmaf(cc.x, h.x, dd.x * xv[j].x);
            y[j].y = fmaf(cc.y, h.y, dd.y * xv[j].y);
            y[j].z = fmaf(cc.z, h.z, dd.z * xv[j].z);
            y[j].w = fmaf(cc.w, h.w, dd.w * xv[j].w);
        }

        float s[4], q[4];
        #pragma unroll
        for (int j = 0; j < 4; j++) {
            s[j] = (y[j].x + y[j].y) + (y[j].z + y[j].w);
            q[j] = fmaf(y[j].x, y[j].x,
                   fmaf(y[j].y, y[j].y,
                   fmaf(y[j].z, y[j].z, y[j].w * y[j].w)));
        }
        #pragma unroll
        for (int o = 16; o > 0; o >>= 1) {
            #pragma unroll
            for (int j = 0; j < 4; j++) {
                s[j] += __shfl_xor_sync(0xffffffffu, s[j], o);
                q[j] += __shfl_xor_sync(0xffffffffu, q[j], o);
            }
        }
        if (lane == 0) {
            #pragma unroll
            for (int j = 0; j < 4; j++)
                red[par][j][wid] = make_float2(s[j], q[j]);
        }
        __syncthreads();

        if (wid == 0) {
            const int j = lane >> 3;   // 0..3
            const int w = lane & 7;    // 0..7
            float2 p = red[par][j][w];
            #pragma unroll
            for (int o = 4; o > 0; o >>= 1) {
                p.x += __shfl_xor_sync(0xffffffffu, p.x, o);
                p.y += __shfl_xor_sync(0xffffffffu, p.y, o);
            }
            if (w == 0) {
                const float mu  = p.x * (1.f / ND);
                const float var = fmaf(-mu, mu, p.y * (1.f / ND));
                mur[par][j] = make_float2(mu, rsqrtf(var + EPS));
            }
        }
        __syncthreads();

        const float4 g4 = __ldg(reinterpret_cast<const float4*>(G + d4));
        const float4 be = __ldg(reinterpret_cast<const float4*>(Be + d4));
        #pragma unroll
        for (int j = 0; j < 4; j++) {
            const float2 mr = mur[par][j];
            float4 o;
            o.x = fmaf((y[j].x - mr.x) * mr.y, g4.x, be.x);
            o.y = fmaf((y[j].y - mr.x) * mr.y, g4.y, be.y);
            o.z = fmaf((y[j].z - mr.x) * mr.y, g4.z, be.z);
            o.w = fmaf((y[j].w - mr.x) * mr.y, g4.w, be.w);
            __stcs(&op[(size_t)(gq * 4 + j) * (ND / 4)], o);
        }
    }
}

extern "C" void kernel_launch(void* const* d_in, const int* in_sizes, int n_in,
                              void* d_out, int out_size) {
    const float* x  = (const float*)d_in[0];
    const float* A  = (const float*)d_in[1];
    const float* B  = (const float*)d_in[2];
    const float* C  = (const float*)d_in[3];
    const float* D  = (const float*)d_in[4];
    const float* G  = (const float*)d_in[5];
    const float* Be = (const float*)d_in[6];
    float* out = (float*)d_out;

    // Kernel boundaries provide the grid-wide ordering; no in-kernel
    // inter-block synchronization anywhere.
    k_chunk<<<HBLK, 256>>>(x, A, B, 0);
    k_fuse <<<HBLK, 256>>>(x, A, B, C, D, G, Be, out, 0);
    k_chunk<<<HBLK, 256>>>(x, A, B, 1);
    k_fuse <<<HBLK, 256>>>(x, A, B, C, D, G, Be, out, 1);
}